// round 4
// baseline (speedup 1.0000x reference)
#include <cuda_runtime.h>
#include <cuda_fp16.h>
#include <cstdint>

// ============================================================
// out[8192,4096] = data[8192,4096] @ (mask*weight)[4096,4096]^T + bias
// Target is BASE sm_100 (no tcgen05/TMA-'a' features available, per ptxas).
// Plan: fp16 operands + mma.sync.m16n8k16 (HMMA) with fp32 accumulators,
//       cp.async 4-stage pipelined SMEM tiles, 256x128x32 CTA tiles.
// ============================================================

static constexpr int M_TOK = 8192;
static constexpr int N_OUT = 4096;
static constexpr int K_IN  = 4096;

static constexpr int BM = 256;
static constexpr int BN = 128;
static constexpr int BK = 32;
static constexpr int STAGES = 4;
static constexpr int KT = K_IN / BK;          // 128

static constexpr int PAD = 8;                 // halves of padding per row
static constexpr int PITCH = BK + PAD;        // 40 halves = 80 bytes
static constexpr int A_HALVES = BM * PITCH;   // 10240
static constexpr int B_HALVES = BN * PITCH;   // 5120
static constexpr int STAGE_HALVES = A_HALVES + B_HALVES;          // 15360
static constexpr int SMEM_BYTES = STAGES * STAGE_HALVES * 2;      // 122880

// ---------------- scratch (fp16 operands) ----------------
__device__ __align__(1024) __half g_Wh[(size_t)N_OUT * K_IN];   // 32 MB
__device__ __align__(1024) __half g_Dh[(size_t)M_TOK * K_IN];   // 64 MB

// ---------------- small PTX helpers (all sm_80+ base features) ----------------
__device__ __forceinline__ void cp_async16(uint32_t smem_addr, const void* gptr) {
    asm volatile("cp.async.cg.shared.global [%0], [%1], 16;"
                 :: "r"(smem_addr), "l"(gptr));
}
__device__ __forceinline__ void cp_commit() {
    asm volatile("cp.async.commit_group;");
}
template <int N>
__device__ __forceinline__ void cp_wait() {
    asm volatile("cp.async.wait_group %0;" :: "n"(N));
}

__device__ __forceinline__ void mma16816(float* d,
                                         const uint32_t* a, const uint32_t* b) {
    asm volatile(
        "mma.sync.aligned.m16n8k16.row.col.f32.f16.f16.f32 "
        "{%0,%1,%2,%3}, {%4,%5,%6,%7}, {%8,%9}, {%0,%1,%2,%3};"
        : "+f"(d[0]), "+f"(d[1]), "+f"(d[2]), "+f"(d[3])
        : "r"(a[0]), "r"(a[1]), "r"(a[2]), "r"(a[3]), "r"(b[0]), "r"(b[1]));
}

// ---------------- conversion kernels ----------------
__global__ void k_maskmul_f16(const float4* __restrict__ w,
                              const float4* __restrict__ m,
                              uint2* __restrict__ out, int n4)
{
    for (int i = blockIdx.x * blockDim.x + threadIdx.x; i < n4; i += gridDim.x * blockDim.x) {
        float4 wv = w[i], mv = m[i];
        __half2 h0 = __floats2half2_rn(wv.x * mv.x, wv.y * mv.y);
        __half2 h1 = __floats2half2_rn(wv.z * mv.z, wv.w * mv.w);
        uint2 r;
        r.x = *reinterpret_cast<unsigned*>(&h0);
        r.y = *reinterpret_cast<unsigned*>(&h1);
        out[i] = r;
    }
}

__global__ void k_cvt_f16(const float4* __restrict__ d,
                          uint2* __restrict__ out, int n4)
{
    for (int i = blockIdx.x * blockDim.x + threadIdx.x; i < n4; i += gridDim.x * blockDim.x) {
        float4 v = d[i];
        __half2 h0 = __floats2half2_rn(v.x, v.y);
        __half2 h1 = __floats2half2_rn(v.z, v.w);
        uint2 r;
        r.x = *reinterpret_cast<unsigned*>(&h0);
        r.y = *reinterpret_cast<unsigned*>(&h1);
        out[i] = r;
    }
}

// ---------------- GEMM: 256x128 CTA tile, 16 warps (4x4), 64x32 warp tile ----
__global__ void __launch_bounds__(512, 1)
gemm_hmma(const __half* __restrict__ Dh,   // [M,K] fp16
          const __half* __restrict__ Wh,   // [N,K] fp16
          const float* __restrict__ bias,
          float* __restrict__ out)
{
    extern __shared__ __half smem[];

    const int tid  = threadIdx.x;
    const int wid  = tid >> 5;
    const int lane = tid & 31;
    const int g    = lane >> 2;   // group id 0..7
    const int q    = lane & 3;    // thread-in-group 0..3
    const int wm   = wid & 3;     // warp M index 0..3 (64 rows each)
    const int wn   = wid >> 2;    // warp N index 0..3 (32 cols each)

    const int m0 = blockIdx.y * BM;
    const int n0 = blockIdx.x * BN;

    const uint32_t sb = (uint32_t)__cvta_generic_to_shared(smem);

    float acc[4][4][4];
    #pragma unroll
    for (int i = 0; i < 4; i++)
        #pragma unroll
        for (int j = 0; j < 4; j++)
            #pragma unroll
            for (int v = 0; v < 4; v++) acc[i][j][v] = 0.0f;

    // -------- async tile loader: A chunks 1024 (2/thread), B chunks 512 (1/thread)
    auto load_stage = [&](int slot, int kt) {
        const int k0 = kt * BK;
        const uint32_t base = sb + (uint32_t)(slot * STAGE_HALVES) * 2;
        // A: chunk c -> row=c>>2, kc=c&3 (8 halves = 16B per chunk)
        #pragma unroll
        for (int rep = 0; rep < 2; rep++) {
            int c = tid + rep * 512;
            int row = c >> 2, kc = c & 3;
            cp_async16(base + (uint32_t)(row * PITCH + kc * 8) * 2,
                       Dh + (size_t)(m0 + row) * K_IN + k0 + kc * 8);
        }
        // B
        {
            int c = tid;
            int row = c >> 2, kc = c & 3;
            cp_async16(base + (uint32_t)(A_HALVES + row * PITCH + kc * 8) * 2,
                       Wh + (size_t)(n0 + row) * K_IN + k0 + kc * 8);
        }
    };

    // -------- prologue: fill STAGES-1 stages
    #pragma unroll
    for (int s = 0; s < STAGES - 1; s++) {
        load_stage(s, s);
        cp_commit();
    }

    // -------- mainloop
    for (int kt = 0; kt < KT; kt++) {
        cp_wait<STAGES - 2>();
        __syncthreads();

        // prefetch the stage STAGES-1 ahead (slot just freed last iteration)
        int next = kt + STAGES - 1;
        if (next < KT) load_stage(next % STAGES, next);
        cp_commit();

        const int slot = kt % STAGES;
        const __half* As = smem + slot * STAGE_HALVES;
        const __half* Bs = As + A_HALVES;

        #pragma unroll
        for (int ks = 0; ks < BK / 16; ks++) {
            const int ko = ks * 16;
            uint32_t a[4][4], b[4][2];
            #pragma unroll
            for (int i = 0; i < 4; i++) {
                const int r0 = wm * 64 + i * 16 + g;
                const __half* p0 = As + r0 * PITCH + ko + q * 2;
                const __half* p1 = As + (r0 + 8) * PITCH + ko + q * 2;
                a[i][0] = *reinterpret_cast<const uint32_t*>(p0);
                a[i][1] = *reinterpret_cast<const uint32_t*>(p1);
                a[i][2] = *reinterpret_cast<const uint32_t*>(p0 + 8);
                a[i][3] = *reinterpret_cast<const uint32_t*>(p1 + 8);
            }
            #pragma unroll
            for (int j = 0; j < 4; j++) {
                const int nr = wn * 32 + j * 8 + g;
                const __half* p = Bs + nr * PITCH + ko + q * 2;
                b[j][0] = *reinterpret_cast<const uint32_t*>(p);
                b[j][1] = *reinterpret_cast<const uint32_t*>(p + 8);
            }
            #pragma unroll
            for (int i = 0; i < 4; i++)
                #pragma unroll
                for (int j = 0; j < 4; j++)
                    mma16816(acc[i][j], a[i], b[j]);
        }
        __syncthreads();
    }
    cp_wait<0>();

    // -------- epilogue: acc + bias -> out (float2 stores, fully coalesced per q-group)
    #pragma unroll
    for (int i = 0; i < 4; i++) {
        const int r0 = m0 + wm * 64 + i * 16 + g;
        #pragma unroll
        for (int j = 0; j < 4; j++) {
            const int c0 = n0 + wn * 32 + j * 8 + q * 2;
            const float2 bv = *reinterpret_cast<const float2*>(bias + c0);
            float2 o0, o1;
            o0.x = acc[i][j][0] + bv.x;
            o0.y = acc[i][j][1] + bv.y;
            o1.x = acc[i][j][2] + bv.x;
            o1.y = acc[i][j][3] + bv.y;
            *reinterpret_cast<float2*>(out + (size_t)r0 * N_OUT + c0) = o0;
            *reinterpret_cast<float2*>(out + (size_t)(r0 + 8) * N_OUT + c0) = o1;
        }
    }
}

// ---------------- host launcher ----------------
extern "C" void kernel_launch(void* const* d_in, const int* in_sizes, int n_in,
                              void* d_out, int out_size)
{
    const float* data   = (const float*)d_in[0];
    const float* weight = (const float*)d_in[1];
    const float* mask   = (const float*)d_in[2];
    const float* bias   = (const float*)d_in[3];
    float* out = (float*)d_out;

    void* pWh = nullptr;
    void* pDh = nullptr;
    cudaGetSymbolAddress(&pWh, g_Wh);
    cudaGetSymbolAddress(&pDh, g_Dh);

    // Pass 1: fp16 conversion
    k_maskmul_f16<<<2048, 256>>>((const float4*)weight, (const float4*)mask,
                                 (uint2*)pWh, (N_OUT * K_IN) / 4);
    k_cvt_f16<<<2048, 256>>>((const float4*)data, (uint2*)pDh, (M_TOK * K_IN) / 4);

    // Pass 2: HMMA GEMM
    static bool attr_set = false;
    if (!attr_set) {
        cudaFuncSetAttribute(gemm_hmma,
                             cudaFuncAttributeMaxDynamicSharedMemorySize, SMEM_BYTES);
        attr_set = true;
    }
    dim3 grid(N_OUT / BN, M_TOK / BM);   // (32, 32) = 1024 CTAs
    gemm_hmma<<<grid, 512, SMEM_BYTES>>>((const __half*)pDh, (const __half*)pWh,
                                         bias, out);
}

// round 6
// speedup vs baseline: 1.2471x; 1.2471x over previous
#include <cuda_runtime.h>
#include <cuda_fp16.h>
#include <cstdint>

// ============================================================
// out[8192,4096] = data[8192,4096] @ (mask*weight)[4096,4096]^T + bias
// Base sm_100 ISA (no tcgen05). fp16 HMMA mma.sync.m16n8k16, fp32 accum.
// R6 = R5 resubmit (suspected infra flake) minus the static-bool guard:
//   - ldmatrix.x4 fragment loads (24 scalar LDS -> 6 LDSM per warp-ks)
//   - dummy first launch aligns ncu's "-s 5 -c 1" window onto the GEMM
//   - cudaFuncSetAttribute called unconditionally (no static state)
// ============================================================

static constexpr int M_TOK = 8192;
static constexpr int N_OUT = 4096;
static constexpr int K_IN  = 4096;

static constexpr int BM = 256;
static constexpr int BN = 128;
static constexpr int BK = 32;
static constexpr int STAGES = 4;
static constexpr int KT = K_IN / BK;          // 128

static constexpr int PAD = 8;                 // halves of padding per row
static constexpr int PITCH = BK + PAD;        // 40 halves = 80 bytes (20 banks)
static constexpr int A_HALVES = BM * PITCH;   // 10240
static constexpr int B_HALVES = BN * PITCH;   // 5120
static constexpr int STAGE_HALVES = A_HALVES + B_HALVES;          // 15360
static constexpr int SMEM_BYTES = STAGES * STAGE_HALVES * 2;      // 122880

// ---------------- scratch (fp16 operands) ----------------
__device__ __align__(1024) __half g_Wh[(size_t)N_OUT * K_IN];   // 32 MB
__device__ __align__(1024) __half g_Dh[(size_t)M_TOK * K_IN];   // 64 MB

// ---------------- PTX helpers (sm_80 base features only) ----------------
__device__ __forceinline__ void cp_async16(uint32_t smem_addr, const void* gptr) {
    asm volatile("cp.async.cg.shared.global [%0], [%1], 16;"
                 :: "r"(smem_addr), "l"(gptr));
}
__device__ __forceinline__ void cp_commit() {
    asm volatile("cp.async.commit_group;");
}
template <int N>
__device__ __forceinline__ void cp_wait() {
    asm volatile("cp.async.wait_group %0;" :: "n"(N));
}

#define LDSM_X4(r, addr) \
    asm volatile("ldmatrix.sync.aligned.m8n8.x4.shared.b16 {%0,%1,%2,%3}, [%4];" \
        : "=r"((r)[0]), "=r"((r)[1]), "=r"((r)[2]), "=r"((r)[3]) : "r"(addr))

__device__ __forceinline__ void mma16816(float* d,
                                         const uint32_t* a, const uint32_t* b) {
    asm volatile(
        "mma.sync.aligned.m16n8k16.row.col.f32.f16.f16.f32 "
        "{%0,%1,%2,%3}, {%4,%5,%6,%7}, {%8,%9}, {%0,%1,%2,%3};"
        : "+f"(d[0]), "+f"(d[1]), "+f"(d[2]), "+f"(d[3])
        : "r"(a[0]), "r"(a[1]), "r"(a[2]), "r"(a[3]), "r"(b[0]), "r"(b[1]));
}

// ---------------- dummy kernel (ncu capture-window alignment) -------------
__global__ void k_nop() {}

// ---------------- conversion kernels ----------------
__global__ void k_maskmul_f16(const float4* __restrict__ w,
                              const float4* __restrict__ m,
                              uint2* __restrict__ out, int n4)
{
    for (int i = blockIdx.x * blockDim.x + threadIdx.x; i < n4; i += gridDim.x * blockDim.x) {
        float4 wv = w[i], mv = m[i];
        __half2 h0 = __floats2half2_rn(wv.x * mv.x, wv.y * mv.y);
        __half2 h1 = __floats2half2_rn(wv.z * mv.z, wv.w * mv.w);
        uint2 r;
        r.x = *reinterpret_cast<unsigned*>(&h0);
        r.y = *reinterpret_cast<unsigned*>(&h1);
        out[i] = r;
    }
}

__global__ void k_cvt_f16(const float4* __restrict__ d,
                          uint2* __restrict__ out, int n4)
{
    for (int i = blockIdx.x * blockDim.x + threadIdx.x; i < n4; i += gridDim.x * blockDim.x) {
        float4 v = d[i];
        __half2 h0 = __floats2half2_rn(v.x, v.y);
        __half2 h1 = __floats2half2_rn(v.z, v.w);
        uint2 r;
        r.x = *reinterpret_cast<unsigned*>(&h0);
        r.y = *reinterpret_cast<unsigned*>(&h1);
        out[i] = r;
    }
}

// ---------------- GEMM: 256x128 CTA tile, 16 warps (4x4), 64x32 warp tile ----
__global__ void __launch_bounds__(512, 1)
gemm_hmma(const __half* __restrict__ Dh,   // [M,K] fp16
          const __half* __restrict__ Wh,   // [N,K] fp16
          const float* __restrict__ bias,
          float* __restrict__ out)
{
    extern __shared__ __half smem[];

    const int tid  = threadIdx.x;
    const int wid  = tid >> 5;
    const int lane = tid & 31;
    const int g    = lane >> 2;   // group id 0..7
    const int q    = lane & 3;    // thread-in-group 0..3
    const int wm   = wid & 3;     // warp M index 0..3 (64 rows each)
    const int wn   = wid >> 2;    // warp N index 0..3 (32 cols each)

    const int m0 = blockIdx.y * BM;
    const int n0 = blockIdx.x * BN;

    const uint32_t sb = (uint32_t)__cvta_generic_to_shared(smem);

    // ldmatrix per-lane source rows.
    // A x4 (matrix order -> regs a0..a3): (rows0-7,k0),(rows8-15,k0),(rows0-7,k8),(rows8-15,k8)
    const int a_row = ((lane >> 3) & 1) * 8 + (lane & 7);
    const int a_k   = ((lane >> 4) & 1) * 8;
    // B x4 (matrix order -> regs b0..b3): (n j0,k0),(n j0,k8),(n j0+8,k0),(n j0+8,k8)
    const int b_n   = ((lane >> 4) & 1) * 8 + (lane & 7);
    const int b_k   = ((lane >> 3) & 1) * 8;

    const uint32_t a_lm_off = (uint32_t)((wm * 64 + a_row) * PITCH + a_k) * 2;
    const uint32_t b_lm_off = (uint32_t)(A_HALVES + (wn * 32 + b_n) * PITCH + b_k) * 2;

    float acc[4][4][4];
    #pragma unroll
    for (int i = 0; i < 4; i++)
        #pragma unroll
        for (int j = 0; j < 4; j++)
            #pragma unroll
            for (int v = 0; v < 4; v++) acc[i][j][v] = 0.0f;

    // -------- async tile loader: A 1024 chunks (2/thread), B 512 chunks (1/thread)
    auto load_stage = [&](int slot, int kt) {
        const int k0 = kt * BK;
        const uint32_t base = sb + (uint32_t)(slot * STAGE_HALVES) * 2;
        #pragma unroll
        for (int rep = 0; rep < 2; rep++) {
            int c = tid + rep * 512;
            int row = c >> 2, kc = c & 3;
            cp_async16(base + (uint32_t)(row * PITCH + kc * 8) * 2,
                       Dh + (size_t)(m0 + row) * K_IN + k0 + kc * 8);
        }
        {
            int c = tid;
            int row = c >> 2, kc = c & 3;
            cp_async16(base + (uint32_t)(A_HALVES + row * PITCH + kc * 8) * 2,
                       Wh + (size_t)(n0 + row) * K_IN + k0 + kc * 8);
        }
    };

    // -------- prologue
    #pragma unroll
    for (int s = 0; s < STAGES - 1; s++) {
        load_stage(s, s);
        cp_commit();
    }

    // -------- mainloop
    for (int kt = 0; kt < KT; kt++) {
        cp_wait<STAGES - 2>();
        __syncthreads();

        int next = kt + STAGES - 1;
        if (next < KT) load_stage(next % STAGES, next);
        cp_commit();

        const int slot = kt % STAGES;
        const uint32_t stage = sb + (uint32_t)(slot * STAGE_HALVES) * 2;
        const uint32_t a_base = stage + a_lm_off;
        const uint32_t b_base = stage + b_lm_off;

        #pragma unroll
        for (int ks = 0; ks < BK / 16; ks++) {
            const uint32_t ko = (uint32_t)(ks * 16) * 2;   // byte offset
            uint32_t a[4][4], b[2][4];
            #pragma unroll
            for (int i = 0; i < 4; i++)
                LDSM_X4(a[i], a_base + (uint32_t)(i * 16 * PITCH) * 2 + ko);
            #pragma unroll
            for (int jp = 0; jp < 2; jp++)
                LDSM_X4(b[jp], b_base + (uint32_t)(jp * 16 * PITCH) * 2 + ko);
            #pragma unroll
            for (int i = 0; i < 4; i++)
                #pragma unroll
                for (int j = 0; j < 4; j++)
                    mma16816(acc[i][j], a[i], &b[j >> 1][(j & 1) * 2]);
        }
        __syncthreads();
    }
    cp_wait<0>();

    // -------- epilogue: acc + bias -> out (float2 stores)
    #pragma unroll
    for (int i = 0; i < 4; i++) {
        const int r0 = m0 + wm * 64 + i * 16 + g;
        #pragma unroll
        for (int j = 0; j < 4; j++) {
            const int c0 = n0 + wn * 32 + j * 8 + q * 2;
            const float2 bv = *reinterpret_cast<const float2*>(bias + c0);
            float2 o0, o1;
            o0.x = acc[i][j][0] + bv.x;
            o0.y = acc[i][j][1] + bv.y;
            o1.x = acc[i][j][2] + bv.x;
            o1.y = acc[i][j][3] + bv.y;
            *reinterpret_cast<float2*>(out + (size_t)r0 * N_OUT + c0) = o0;
            *reinterpret_cast<float2*>(out + (size_t)(r0 + 8) * N_OUT + c0) = o1;
        }
    }
}

// ---------------- host launcher ----------------
extern "C" void kernel_launch(void* const* d_in, const int* in_sizes, int n_in,
                              void* d_out, int out_size)
{
    const float* data   = (const float*)d_in[0];
    const float* weight = (const float*)d_in[1];
    const float* mask   = (const float*)d_in[2];
    const float* bias   = (const float*)d_in[3];
    float* out = (float*)d_out;

    void* pWh = nullptr;
    void* pDh = nullptr;
    cudaGetSymbolAddress(&pWh, g_Wh);
    cudaGetSymbolAddress(&pDh, g_Dh);

    // Dummy launch: shifts ncu's fixed "-s 5 -c 1" capture window so the
    // profiled launch is the GEMM, not the convert kernel.
    k_nop<<<1, 32>>>();

    // Pass 1: fp16 conversion
    k_maskmul_f16<<<2048, 256>>>((const float4*)weight, (const float4*)mask,
                                 (uint2*)pWh, (N_OUT * K_IN) / 4);
    k_cvt_f16<<<2048, 256>>>((const float4*)data, (uint2*)pDh, (M_TOK * K_IN) / 4);

    // Pass 2: HMMA GEMM (attribute set unconditionally; no static state)
    cudaFuncSetAttribute(gemm_hmma,
                         cudaFuncAttributeMaxDynamicSharedMemorySize, SMEM_BYTES);
    dim3 grid(N_OUT / BN, M_TOK / BM);   // (32, 32) = 1024 CTAs
    gemm_hmma<<<grid, 512, SMEM_BYTES>>>((const __half*)pDh, (const __half*)pWh,
                                         bias, out);
}

// round 7
// speedup vs baseline: 1.2493x; 1.0018x over previous
#include <cuda_runtime.h>
#include <cuda_fp16.h>
#include <cstdint>

// ============================================================
// out[8192,4096] = data[8192,4096] @ (mask*weight)[4096,4096]^T + bias
// Base sm_100 ISA (no tcgen05). fp16 HMMA mma.sync.m16n8k16, fp32 accum.
// R6 = R5 resubmit (suspected infra flake) minus the static-bool guard:
//   - ldmatrix.x4 fragment loads (24 scalar LDS -> 6 LDSM per warp-ks)
//   - dummy first launch aligns ncu's "-s 5 -c 1" window onto the GEMM
//   - cudaFuncSetAttribute called unconditionally (no static state)
// ============================================================

static constexpr int M_TOK = 8192;
static constexpr int N_OUT = 4096;
static constexpr int K_IN  = 4096;

static constexpr int BM = 256;
static constexpr int BN = 128;
static constexpr int BK = 32;
static constexpr int STAGES = 4;
static constexpr int KT = K_IN / BK;          // 128

static constexpr int PAD = 8;                 // halves of padding per row
static constexpr int PITCH = BK + PAD;        // 40 halves = 80 bytes (20 banks)
static constexpr int A_HALVES = BM * PITCH;   // 10240
static constexpr int B_HALVES = BN * PITCH;   // 5120
static constexpr int STAGE_HALVES = A_HALVES + B_HALVES;          // 15360
static constexpr int SMEM_BYTES = STAGES * STAGE_HALVES * 2;      // 122880

// ---------------- scratch (fp16 operands) ----------------
__device__ __align__(1024) __half g_Wh[(size_t)N_OUT * K_IN];   // 32 MB
__device__ __align__(1024) __half g_Dh[(size_t)M_TOK * K_IN];   // 64 MB

// ---------------- PTX helpers (sm_80 base features only) ----------------
__device__ __forceinline__ void cp_async16(uint32_t smem_addr, const void* gptr) {
    asm volatile("cp.async.cg.shared.global [%0], [%1], 16;"
                 :: "r"(smem_addr), "l"(gptr));
}
__device__ __forceinline__ void cp_commit() {
    asm volatile("cp.async.commit_group;");
}
template <int N>
__device__ __forceinline__ void cp_wait() {
    asm volatile("cp.async.wait_group %0;" :: "n"(N));
}

#define LDSM_X4(r, addr) \
    asm volatile("ldmatrix.sync.aligned.m8n8.x4.shared.b16 {%0,%1,%2,%3}, [%4];" \
        : "=r"((r)[0]), "=r"((r)[1]), "=r"((r)[2]), "=r"((r)[3]) : "r"(addr))

__device__ __forceinline__ void mma16816(float* d,
                                         const uint32_t* a, const uint32_t* b) {
    asm volatile(
        "mma.sync.aligned.m16n8k16.row.col.f32.f16.f16.f32 "
        "{%0,%1,%2,%3}, {%4,%5,%6,%7}, {%8,%9}, {%0,%1,%2,%3};"
        : "+f"(d[0]), "+f"(d[1]), "+f"(d[2]), "+f"(d[3])
        : "r"(a[0]), "r"(a[1]), "r"(a[2]), "r"(a[3]), "r"(b[0]), "r"(b[1]));
}

// ---------------- dummy kernel (ncu capture-window alignment) -------------
__global__ void k_nop() {}

// ---------------- conversion kernels ----------------
__global__ void k_maskmul_f16(const float4* __restrict__ w,
                              const float4* __restrict__ m,
                              uint2* __restrict__ out, int n4)
{
    for (int i = blockIdx.x * blockDim.x + threadIdx.x; i < n4; i += gridDim.x * blockDim.x) {
        float4 wv = w[i], mv = m[i];
        __half2 h0 = __floats2half2_rn(wv.x * mv.x, wv.y * mv.y);
        __half2 h1 = __floats2half2_rn(wv.z * mv.z, wv.w * mv.w);
        uint2 r;
        r.x = *reinterpret_cast<unsigned*>(&h0);
        r.y = *reinterpret_cast<unsigned*>(&h1);
        out[i] = r;
    }
}

__global__ void k_cvt_f16(const float4* __restrict__ d,
                          uint2* __restrict__ out, int n4)
{
    for (int i = blockIdx.x * blockDim.x + threadIdx.x; i < n4; i += gridDim.x * blockDim.x) {
        float4 v = d[i];
        __half2 h0 = __floats2half2_rn(v.x, v.y);
        __half2 h1 = __floats2half2_rn(v.z, v.w);
        uint2 r;
        r.x = *reinterpret_cast<unsigned*>(&h0);
        r.y = *reinterpret_cast<unsigned*>(&h1);
        out[i] = r;
    }
}

// ---------------- GEMM: 256x128 CTA tile, 16 warps (4x4), 64x32 warp tile ----
__global__ void __launch_bounds__(512, 1)
gemm_hmma(const __half* __restrict__ Dh,   // [M,K] fp16
          const __half* __restrict__ Wh,   // [N,K] fp16
          const float* __restrict__ bias,
          float* __restrict__ out)
{
    extern __shared__ __half smem[];

    const int tid  = threadIdx.x;
    const int wid  = tid >> 5;
    const int lane = tid & 31;
    const int g    = lane >> 2;   // group id 0..7
    const int q    = lane & 3;    // thread-in-group 0..3
    const int wm   = wid & 3;     // warp M index 0..3 (64 rows each)
    const int wn   = wid >> 2;    // warp N index 0..3 (32 cols each)

    const int m0 = blockIdx.y * BM;
    const int n0 = blockIdx.x * BN;

    const uint32_t sb = (uint32_t)__cvta_generic_to_shared(smem);

    // ldmatrix per-lane source rows.
    // A x4 (matrix order -> regs a0..a3): (rows0-7,k0),(rows8-15,k0),(rows0-7,k8),(rows8-15,k8)
    const int a_row = ((lane >> 3) & 1) * 8 + (lane & 7);
    const int a_k   = ((lane >> 4) & 1) * 8;
    // B x4 (matrix order -> regs b0..b3): (n j0,k0),(n j0,k8),(n j0+8,k0),(n j0+8,k8)
    const int b_n   = ((lane >> 4) & 1) * 8 + (lane & 7);
    const int b_k   = ((lane >> 3) & 1) * 8;

    const uint32_t a_lm_off = (uint32_t)((wm * 64 + a_row) * PITCH + a_k) * 2;
    const uint32_t b_lm_off = (uint32_t)(A_HALVES + (wn * 32 + b_n) * PITCH + b_k) * 2;

    float acc[4][4][4];
    #pragma unroll
    for (int i = 0; i < 4; i++)
        #pragma unroll
        for (int j = 0; j < 4; j++)
            #pragma unroll
            for (int v = 0; v < 4; v++) acc[i][j][v] = 0.0f;

    // -------- async tile loader: A 1024 chunks (2/thread), B 512 chunks (1/thread)
    auto load_stage = [&](int slot, int kt) {
        const int k0 = kt * BK;
        const uint32_t base = sb + (uint32_t)(slot * STAGE_HALVES) * 2;
        #pragma unroll
        for (int rep = 0; rep < 2; rep++) {
            int c = tid + rep * 512;
            int row = c >> 2, kc = c & 3;
            cp_async16(base + (uint32_t)(row * PITCH + kc * 8) * 2,
                       Dh + (size_t)(m0 + row) * K_IN + k0 + kc * 8);
        }
        {
            int c = tid;
            int row = c >> 2, kc = c & 3;
            cp_async16(base + (uint32_t)(A_HALVES + row * PITCH + kc * 8) * 2,
                       Wh + (size_t)(n0 + row) * K_IN + k0 + kc * 8);
        }
    };

    // -------- prologue
    #pragma unroll
    for (int s = 0; s < STAGES - 1; s++) {
        load_stage(s, s);
        cp_commit();
    }

    // -------- mainloop
    for (int kt = 0; kt < KT; kt++) {
        cp_wait<STAGES - 2>();
        __syncthreads();

        int next = kt + STAGES - 1;
        if (next < KT) load_stage(next % STAGES, next);
        cp_commit();

        const int slot = kt % STAGES;
        const uint32_t stage = sb + (uint32_t)(slot * STAGE_HALVES) * 2;
        const uint32_t a_base = stage + a_lm_off;
        const uint32_t b_base = stage + b_lm_off;

        #pragma unroll
        for (int ks = 0; ks < BK / 16; ks++) {
            const uint32_t ko = (uint32_t)(ks * 16) * 2;   // byte offset
            uint32_t a[4][4], b[2][4];
            #pragma unroll
            for (int i = 0; i < 4; i++)
                LDSM_X4(a[i], a_base + (uint32_t)(i * 16 * PITCH) * 2 + ko);
            #pragma unroll
            for (int jp = 0; jp < 2; jp++)
                LDSM_X4(b[jp], b_base + (uint32_t)(jp * 16 * PITCH) * 2 + ko);
            #pragma unroll
            for (int i = 0; i < 4; i++)
                #pragma unroll
                for (int j = 0; j < 4; j++)
                    mma16816(acc[i][j], a[i], &b[j >> 1][(j & 1) * 2]);
        }
        __syncthreads();
    }
    cp_wait<0>();

    // -------- epilogue: acc + bias -> out (float2 stores)
    #pragma unroll
    for (int i = 0; i < 4; i++) {
        const int r0 = m0 + wm * 64 + i * 16 + g;
        #pragma unroll
        for (int j = 0; j < 4; j++) {
            const int c0 = n0 + wn * 32 + j * 8 + q * 2;
            const float2 bv = *reinterpret_cast<const float2*>(bias + c0);
            float2 o0, o1;
            o0.x = acc[i][j][0] + bv.x;
            o0.y = acc[i][j][1] + bv.y;
            o1.x = acc[i][j][2] + bv.x;
            o1.y = acc[i][j][3] + bv.y;
            *reinterpret_cast<float2*>(out + (size_t)r0 * N_OUT + c0) = o0;
            *reinterpret_cast<float2*>(out + (size_t)(r0 + 8) * N_OUT + c0) = o1;
        }
    }
}

// ---------------- host launcher ----------------
extern "C" void kernel_launch(void* const* d_in, const int* in_sizes, int n_in,
                              void* d_out, int out_size)
{
    const float* data   = (const float*)d_in[0];
    const float* weight = (const float*)d_in[1];
    const float* mask   = (const float*)d_in[2];
    const float* bias   = (const float*)d_in[3];
    float* out = (float*)d_out;

    void* pWh = nullptr;
    void* pDh = nullptr;
    cudaGetSymbolAddress(&pWh, g_Wh);
    cudaGetSymbolAddress(&pDh, g_Dh);

    // Dummy launch: shifts ncu's fixed "-s 5 -c 1" capture window so the
    // profiled launch is the GEMM, not the convert kernel.
    k_nop<<<1, 32>>>();

    // Pass 1: fp16 conversion
    k_maskmul_f16<<<2048, 256>>>((const float4*)weight, (const float4*)mask,
                                 (uint2*)pWh, (N_OUT * K_IN) / 4);
    k_cvt_f16<<<2048, 256>>>((const float4*)data, (uint2*)pDh, (M_TOK * K_IN) / 4);

    // Pass 2: HMMA GEMM (attribute set unconditionally; no static state)
    cudaFuncSetAttribute(gemm_hmma,
                         cudaFuncAttributeMaxDynamicSharedMemorySize, SMEM_BYTES);
    dim3 grid(N_OUT / BN, M_TOK / BM);   // (32, 32) = 1024 CTAs
    gemm_hmma<<<grid, 512, SMEM_BYTES>>>((const __half*)pDh, (const __half*)pWh,
                                         bias, out);
}

// round 8
// speedup vs baseline: 1.2494x; 1.0000x over previous
#include <cuda_runtime.h>
#include <cuda_fp16.h>
#include <cstdint>

// ============================================================
// out[8192,4096] = data[8192,4096] @ (mask*weight)[4096,4096]^T + bias
// Base sm_100 ISA (no tcgen05). fp16 HMMA mma.sync.m16n8k16, fp32 accum.
// R6 = R5 resubmit (suspected infra flake) minus the static-bool guard:
//   - ldmatrix.x4 fragment loads (24 scalar LDS -> 6 LDSM per warp-ks)
//   - dummy first launch aligns ncu's "-s 5 -c 1" window onto the GEMM
//   - cudaFuncSetAttribute called unconditionally (no static state)
// ============================================================

static constexpr int M_TOK = 8192;
static constexpr int N_OUT = 4096;
static constexpr int K_IN  = 4096;

static constexpr int BM = 256;
static constexpr int BN = 128;
static constexpr int BK = 32;
static constexpr int STAGES = 4;
static constexpr int KT = K_IN / BK;          // 128

static constexpr int PAD = 8;                 // halves of padding per row
static constexpr int PITCH = BK + PAD;        // 40 halves = 80 bytes (20 banks)
static constexpr int A_HALVES = BM * PITCH;   // 10240
static constexpr int B_HALVES = BN * PITCH;   // 5120
static constexpr int STAGE_HALVES = A_HALVES + B_HALVES;          // 15360
static constexpr int SMEM_BYTES = STAGES * STAGE_HALVES * 2;      // 122880

// ---------------- scratch (fp16 operands) ----------------
__device__ __align__(1024) __half g_Wh[(size_t)N_OUT * K_IN];   // 32 MB
__device__ __align__(1024) __half g_Dh[(size_t)M_TOK * K_IN];   // 64 MB

// ---------------- PTX helpers (sm_80 base features only) ----------------
__device__ __forceinline__ void cp_async16(uint32_t smem_addr, const void* gptr) {
    asm volatile("cp.async.cg.shared.global [%0], [%1], 16;"
                 :: "r"(smem_addr), "l"(gptr));
}
__device__ __forceinline__ void cp_commit() {
    asm volatile("cp.async.commit_group;");
}
template <int N>
__device__ __forceinline__ void cp_wait() {
    asm volatile("cp.async.wait_group %0;" :: "n"(N));
}

#define LDSM_X4(r, addr) \
    asm volatile("ldmatrix.sync.aligned.m8n8.x4.shared.b16 {%0,%1,%2,%3}, [%4];" \
        : "=r"((r)[0]), "=r"((r)[1]), "=r"((r)[2]), "=r"((r)[3]) : "r"(addr))

__device__ __forceinline__ void mma16816(float* d,
                                         const uint32_t* a, const uint32_t* b) {
    asm volatile(
        "mma.sync.aligned.m16n8k16.row.col.f32.f16.f16.f32 "
        "{%0,%1,%2,%3}, {%4,%5,%6,%7}, {%8,%9}, {%0,%1,%2,%3};"
        : "+f"(d[0]), "+f"(d[1]), "+f"(d[2]), "+f"(d[3])
        : "r"(a[0]), "r"(a[1]), "r"(a[2]), "r"(a[3]), "r"(b[0]), "r"(b[1]));
}

// ---------------- dummy kernel (ncu capture-window alignment) -------------
__global__ void k_nop() {}

// ---------------- conversion kernels ----------------
__global__ void k_maskmul_f16(const float4* __restrict__ w,
                              const float4* __restrict__ m,
                              uint2* __restrict__ out, int n4)
{
    for (int i = blockIdx.x * blockDim.x + threadIdx.x; i < n4; i += gridDim.x * blockDim.x) {
        float4 wv = w[i], mv = m[i];
        __half2 h0 = __floats2half2_rn(wv.x * mv.x, wv.y * mv.y);
        __half2 h1 = __floats2half2_rn(wv.z * mv.z, wv.w * mv.w);
        uint2 r;
        r.x = *reinterpret_cast<unsigned*>(&h0);
        r.y = *reinterpret_cast<unsigned*>(&h1);
        out[i] = r;
    }
}

__global__ void k_cvt_f16(const float4* __restrict__ d,
                          uint2* __restrict__ out, int n4)
{
    for (int i = blockIdx.x * blockDim.x + threadIdx.x; i < n4; i += gridDim.x * blockDim.x) {
        float4 v = d[i];
        __half2 h0 = __floats2half2_rn(v.x, v.y);
        __half2 h1 = __floats2half2_rn(v.z, v.w);
        uint2 r;
        r.x = *reinterpret_cast<unsigned*>(&h0);
        r.y = *reinterpret_cast<unsigned*>(&h1);
        out[i] = r;
    }
}

// ---------------- GEMM: 256x128 CTA tile, 16 warps (4x4), 64x32 warp tile ----
__global__ void __launch_bounds__(512, 1)
gemm_hmma(const __half* __restrict__ Dh,   // [M,K] fp16
          const __half* __restrict__ Wh,   // [N,K] fp16
          const float* __restrict__ bias,
          float* __restrict__ out)
{
    extern __shared__ __half smem[];

    const int tid  = threadIdx.x;
    const int wid  = tid >> 5;
    const int lane = tid & 31;
    const int g    = lane >> 2;   // group id 0..7
    const int q    = lane & 3;    // thread-in-group 0..3
    const int wm   = wid & 3;     // warp M index 0..3 (64 rows each)
    const int wn   = wid >> 2;    // warp N index 0..3 (32 cols each)

    const int m0 = blockIdx.y * BM;
    const int n0 = blockIdx.x * BN;

    const uint32_t sb = (uint32_t)__cvta_generic_to_shared(smem);

    // ldmatrix per-lane source rows.
    // A x4 (matrix order -> regs a0..a3): (rows0-7,k0),(rows8-15,k0),(rows0-7,k8),(rows8-15,k8)
    const int a_row = ((lane >> 3) & 1) * 8 + (lane & 7);
    const int a_k   = ((lane >> 4) & 1) * 8;
    // B x4 (matrix order -> regs b0..b3): (n j0,k0),(n j0,k8),(n j0+8,k0),(n j0+8,k8)
    const int b_n   = ((lane >> 4) & 1) * 8 + (lane & 7);
    const int b_k   = ((lane >> 3) & 1) * 8;

    const uint32_t a_lm_off = (uint32_t)((wm * 64 + a_row) * PITCH + a_k) * 2;
    const uint32_t b_lm_off = (uint32_t)(A_HALVES + (wn * 32 + b_n) * PITCH + b_k) * 2;

    float acc[4][4][4];
    #pragma unroll
    for (int i = 0; i < 4; i++)
        #pragma unroll
        for (int j = 0; j < 4; j++)
            #pragma unroll
            for (int v = 0; v < 4; v++) acc[i][j][v] = 0.0f;

    // -------- async tile loader: A 1024 chunks (2/thread), B 512 chunks (1/thread)
    auto load_stage = [&](int slot, int kt) {
        const int k0 = kt * BK;
        const uint32_t base = sb + (uint32_t)(slot * STAGE_HALVES) * 2;
        #pragma unroll
        for (int rep = 0; rep < 2; rep++) {
            int c = tid + rep * 512;
            int row = c >> 2, kc = c & 3;
            cp_async16(base + (uint32_t)(row * PITCH + kc * 8) * 2,
                       Dh + (size_t)(m0 + row) * K_IN + k0 + kc * 8);
        }
        {
            int c = tid;
            int row = c >> 2, kc = c & 3;
            cp_async16(base + (uint32_t)(A_HALVES + row * PITCH + kc * 8) * 2,
                       Wh + (size_t)(n0 + row) * K_IN + k0 + kc * 8);
        }
    };

    // -------- prologue
    #pragma unroll
    for (int s = 0; s < STAGES - 1; s++) {
        load_stage(s, s);
        cp_commit();
    }

    // -------- mainloop
    for (int kt = 0; kt < KT; kt++) {
        cp_wait<STAGES - 2>();
        __syncthreads();

        int next = kt + STAGES - 1;
        if (next < KT) load_stage(next % STAGES, next);
        cp_commit();

        const int slot = kt % STAGES;
        const uint32_t stage = sb + (uint32_t)(slot * STAGE_HALVES) * 2;
        const uint32_t a_base = stage + a_lm_off;
        const uint32_t b_base = stage + b_lm_off;

        #pragma unroll
        for (int ks = 0; ks < BK / 16; ks++) {
            const uint32_t ko = (uint32_t)(ks * 16) * 2;   // byte offset
            uint32_t a[4][4], b[2][4];
            #pragma unroll
            for (int i = 0; i < 4; i++)
                LDSM_X4(a[i], a_base + (uint32_t)(i * 16 * PITCH) * 2 + ko);
            #pragma unroll
            for (int jp = 0; jp < 2; jp++)
                LDSM_X4(b[jp], b_base + (uint32_t)(jp * 16 * PITCH) * 2 + ko);
            #pragma unroll
            for (int i = 0; i < 4; i++)
                #pragma unroll
                for (int j = 0; j < 4; j++)
                    mma16816(acc[i][j], a[i], &b[j >> 1][(j & 1) * 2]);
        }
        __syncthreads();
    }
    cp_wait<0>();

    // -------- epilogue: acc + bias -> out (float2 stores)
    #pragma unroll
    for (int i = 0; i < 4; i++) {
        const int r0 = m0 + wm * 64 + i * 16 + g;
        #pragma unroll
        for (int j = 0; j < 4; j++) {
            const int c0 = n0 + wn * 32 + j * 8 + q * 2;
            const float2 bv = *reinterpret_cast<const float2*>(bias + c0);
            float2 o0, o1;
            o0.x = acc[i][j][0] + bv.x;
            o0.y = acc[i][j][1] + bv.y;
            o1.x = acc[i][j][2] + bv.x;
            o1.y = acc[i][j][3] + bv.y;
            *reinterpret_cast<float2*>(out + (size_t)r0 * N_OUT + c0) = o0;
            *reinterpret_cast<float2*>(out + (size_t)(r0 + 8) * N_OUT + c0) = o1;
        }
    }
}

// ---------------- host launcher ----------------
extern "C" void kernel_launch(void* const* d_in, const int* in_sizes, int n_in,
                              void* d_out, int out_size)
{
    const float* data   = (const float*)d_in[0];
    const float* weight = (const float*)d_in[1];
    const float* mask   = (const float*)d_in[2];
    const float* bias   = (const float*)d_in[3];
    float* out = (float*)d_out;

    void* pWh = nullptr;
    void* pDh = nullptr;
    cudaGetSymbolAddress(&pWh, g_Wh);
    cudaGetSymbolAddress(&pDh, g_Dh);

    // Dummy launch: shifts ncu's fixed "-s 5 -c 1" capture window so the
    // profiled launch is the GEMM, not the convert kernel.
    k_nop<<<1, 32>>>();

    // Pass 1: fp16 conversion
    k_maskmul_f16<<<2048, 256>>>((const float4*)weight, (const float4*)mask,
                                 (uint2*)pWh, (N_OUT * K_IN) / 4);
    k_cvt_f16<<<2048, 256>>>((const float4*)data, (uint2*)pDh, (M_TOK * K_IN) / 4);

    // Pass 2: HMMA GEMM (attribute set unconditionally; no static state)
    cudaFuncSetAttribute(gemm_hmma,
                         cudaFuncAttributeMaxDynamicSharedMemorySize, SMEM_BYTES);
    dim3 grid(N_OUT / BN, M_TOK / BM);   // (32, 32) = 1024 CTAs
    gemm_hmma<<<grid, 512, SMEM_BYTES>>>((const __half*)pDh, (const __half*)pWh,
                                         bias, out);
}